// round 4
// baseline (speedup 1.0000x reference)
#include <cuda_runtime.h>

#define B  64
#define L  512
#define HB 768
#define HC 1024
#define H  (HB + HC)   // 1792
#define NL 7
#define NCH (H / 128)  // 14 chunks of 128 floats
#define BCH (HB / 128) // 6 bert chunks

// Scratch (no allocations allowed): compaction index + per-row valid count.
__device__ int g_idx[B * L];
__device__ int g_count[B];

// ---------------------------------------------------------------------------
// Kernel 1: per-batch-row stable compaction via warp ballot scan.
// ---------------------------------------------------------------------------
__global__ void build_idx_kernel(const int* __restrict__ valid) {
    int b    = blockIdx.x;
    int lane = threadIdx.x;
    int base = b * L;

    int v[L / 32];
#pragma unroll
    for (int k = 0; k < L / 32; k++)
        v[k] = valid[base + k * 32 + lane];

    int count = 0;
#pragma unroll
    for (int k = 0; k < L / 32; k++) {
        unsigned m = __ballot_sync(0xffffffffu, v[k] != 0);
        if (v[k]) {
            int pos = count + __popc(m & ((1u << lane) - 1u));
            g_idx[base + pos] = k * 32 + lane;
        }
        count += __popc(m);
    }
    if (lane == 0) g_count[b] = count;
}

// ---------------------------------------------------------------------------
// Kernel 2: fused gather + concat + [BL,1792]x[1792,7] matmul + bias.
// TG=4 tokens per warp; lane owns a float4 slice per 128-float chunk.
// Register diet (scalar f32 accumulators, no explicit double buffer) to hit
// 3 blocks/SM = 24 warps: occupancy is the latency-hiding lever this round.
// ---------------------------------------------------------------------------
#define TPB 256
#define WPB (TPB / 32)
#define TG  4
#define OCC 3

__global__ __launch_bounds__(TPB, OCC) void tag_kernel(
    const float* __restrict__ bert,
    const float* __restrict__ comet,
    const float* __restrict__ w,      // [H, NL] row-major
    const float* __restrict__ bias,   // [NL]
    float* __restrict__ out,          // [B, L, NL]
    int total_warps)
{
    extern __shared__ float sW[];     // [NL][H] transposed, 50176 B

    for (int i = threadIdx.x; i < H * NL; i += TPB) {
        int h = i / NL;
        int n = i - h * NL;
        sW[n * H + h] = w[i];
    }
    __syncthreads();

    int lane  = threadIdx.x & 31;
    int warp  = threadIdx.x >> 5;
    int gwarp = blockIdx.x * WPB + warp;
    float bias_r = (lane < NL) ? bias[lane] : 0.0f;
    int hb = lane * 4;

    const int ngroups = (B * L) / TG;  // 8192
    for (int g = gwarp; g < ngroups; g += total_warps) {
        int tok0 = g * TG;
        int b    = tok0 >> 9;          // / L
        int p0   = tok0 & (L - 1);
        int cnt  = g_count[b];

        // 32-bit float-offsets into bert (max 25.2M, fits easily).
        int  boff[TG];
        bool hasb[TG];
#pragma unroll
        for (int t = 0; t < TG; t++) {
            bool v  = (p0 + t) < cnt;
            hasb[t] = v;
            int j   = v ? g_idx[b * L + p0 + t] : 0;
            boff[t] = (b * L + j) * HB;
        }
        const float* crow0 = comet + (size_t)(b * L + p0) * HC;

        float acc[TG][NL];
#pragma unroll
        for (int t = 0; t < TG; t++)
#pragma unroll
            for (int n = 0; n < NL; n++) acc[t][n] = 0.0f;

#pragma unroll
        for (int c = 0; c < NCH; c++) {
            // Token data for this chunk (4 x LDG.128, independent).
            float4 x[TG];
#pragma unroll
            for (int t = 0; t < TG; t++) {
                if (c < BCH) {
                    x[t] = hasb[t]
                        ? *reinterpret_cast<const float4*>(
                              bert + boff[t] + c * 128 + hb)
                        : make_float4(0.0f, 0.0f, 0.0f, 0.0f);
                } else {
                    x[t] = *reinterpret_cast<const float4*>(
                        crow0 + t * HC + (c - BCH) * 128 + hb);
                }
            }

            int h = c * 128 + hb;
#pragma unroll
            for (int n = 0; n < NL; n++) {
                float4 wv = *reinterpret_cast<const float4*>(&sW[n * H + h]);
#pragma unroll
                for (int t = 0; t < TG; t++)
                    acc[t][n] += x[t].x * wv.x + x[t].y * wv.y
                               + x[t].z * wv.z + x[t].w * wv.w;
            }
        }

        // --- butterfly reduce across lanes; lanes 0..6 write logits ---
#pragma unroll
        for (int t = 0; t < TG; t++) {
            float v = 0.0f;
#pragma unroll
            for (int n = 0; n < NL; n++) {
                float s = acc[t][n];
                s += __shfl_xor_sync(0xffffffffu, s, 16);
                s += __shfl_xor_sync(0xffffffffu, s, 8);
                s += __shfl_xor_sync(0xffffffffu, s, 4);
                s += __shfl_xor_sync(0xffffffffu, s, 2);
                s += __shfl_xor_sync(0xffffffffu, s, 1);
                if (lane == n) v = s;   // constant-index select, no spill
            }
            if (lane < NL)
                out[(size_t)(tok0 + t) * NL + lane] = v + bias_r;
        }
    }
}

// ---------------------------------------------------------------------------
extern "C" void kernel_launch(void* const* d_in, const int* in_sizes, int n_in,
                              void* d_out, int out_size) {
    const float* bert  = (const float*)d_in[0];
    const float* comet = (const float*)d_in[1];
    const int*   valid = (const int*)d_in[2];
    const float* w     = (const float*)d_in[3];
    const float* bias  = (const float*)d_in[4];
    float*       out   = (float*)d_out;

    build_idx_kernel<<<B, 32>>>(valid);

    const int smem = H * NL * (int)sizeof(float);  // 50176 B
    cudaFuncSetAttribute(tag_kernel,
                         cudaFuncAttributeMaxDynamicSharedMemorySize, smem);

    const int grid = 148 * OCC;  // 444 blocks = 3/SM, single wave
    tag_kernel<<<grid, TPB, smem>>>(bert, comet, w, bias, out, grid * WPB);
}

// round 5
// speedup vs baseline: 1.0196x; 1.0196x over previous
#include <cuda_runtime.h>

#define B  64
#define L  512
#define HB 768
#define HC 1024
#define H  (HB + HC)   // 1792
#define NL 7
#define NCH (H / 128)  // 14 chunks of 128 floats
#define BCH (HB / 128) // 6 bert chunks
#define SWS (H + 4)    // padded sW stride (1796 mod 32 = 4 -> no bank conflicts)

// Scratch (no allocations allowed): compaction index + per-row valid count.
__device__ int g_idx[B * L];
__device__ int g_count[B];

// ---------------------------------------------------------------------------
// Kernel 1: per-batch-row stable compaction via warp ballot scan.
// ---------------------------------------------------------------------------
__global__ void build_idx_kernel(const int* __restrict__ valid) {
    int b    = blockIdx.x;
    int lane = threadIdx.x;
    int base = b * L;

    int v[L / 32];
#pragma unroll
    for (int k = 0; k < L / 32; k++)
        v[k] = valid[base + k * 32 + lane];

    int count = 0;
#pragma unroll
    for (int k = 0; k < L / 32; k++) {
        unsigned m = __ballot_sync(0xffffffffu, v[k] != 0);
        if (v[k]) {
            int pos = count + __popc(m & ((1u << lane) - 1u));
            g_idx[base + pos] = k * 32 + lane;
        }
        count += __popc(m);
    }
    if (lane == 0) g_count[b] = count;
}

// ---------------------------------------------------------------------------
// Kernel 2: fused gather + concat + [BL,1792]x[1792,7] matmul + bias.
// TG=8 tokens per warp (halves per-token weight-LDS vs TG=4 — the measured
// L1tex wavefront pipe was the upstream throttle on DRAM request rate).
// Scalar f32 accumulators; 2 blocks/SM; grid sized so every warp gets
// EXACTLY 2 groups (perfect balance).
// ---------------------------------------------------------------------------
#define TPB 256
#define WPB (TPB / 32)
#define TG  8
#define OCC 2

__global__ __launch_bounds__(TPB, OCC) void tag_kernel(
    const float* __restrict__ bert,
    const float* __restrict__ comet,
    const float* __restrict__ w,      // [H, NL] row-major
    const float* __restrict__ bias,   // [NL]
    float* __restrict__ out,          // [B, L, NL]
    int total_warps)
{
    extern __shared__ float sW[];     // [NL][SWS] transposed+padded

    for (int i = threadIdx.x; i < H * NL; i += TPB) {
        int h = i / NL;
        int n = i - h * NL;
        sW[n * SWS + h] = w[i];
    }
    __syncthreads();

    int lane  = threadIdx.x & 31;
    int warp  = threadIdx.x >> 5;
    int gwarp = blockIdx.x * WPB + warp;
    float bias_r = (lane < NL) ? bias[lane] : 0.0f;
    int hb = lane * 4;

    const int ngroups = (B * L) / TG;  // 4096
    for (int g = gwarp; g < ngroups; g += total_warps) {
        int tok0 = g * TG;
        int b    = tok0 >> 9;          // / L  (TG divides L, so same row)
        int p0   = tok0 & (L - 1);
        int cnt  = g_count[b];

        // 32-bit float-offsets into bert (max ~25M, fits int).
        int  boff[TG];
        bool hasb[TG];
#pragma unroll
        for (int t = 0; t < TG; t++) {
            bool v  = (p0 + t) < cnt;
            hasb[t] = v;
            int j   = v ? g_idx[b * L + p0 + t] : 0;
            boff[t] = (b * L + j) * HB;
        }
        const float* crow0 = comet + (size_t)(b * L + p0) * HC;

        float acc[TG][NL];
#pragma unroll
        for (int t = 0; t < TG; t++)
#pragma unroll
            for (int n = 0; n < NL; n++) acc[t][n] = 0.0f;

#pragma unroll
        for (int c = 0; c < NCH; c++) {
            // Token data for this chunk: 8 independent LDG.128.
            float4 x[TG];
#pragma unroll
            for (int t = 0; t < TG; t++) {
                if (c < BCH) {
                    x[t] = hasb[t]
                        ? *reinterpret_cast<const float4*>(
                              bert + boff[t] + c * 128 + hb)
                        : make_float4(0.0f, 0.0f, 0.0f, 0.0f);
                } else {
                    x[t] = *reinterpret_cast<const float4*>(
                        crow0 + t * HC + (c - BCH) * 128 + hb);
                }
            }

            int h = c * 128 + hb;
#pragma unroll
            for (int n = 0; n < NL; n++) {
                float4 wv = *reinterpret_cast<const float4*>(&sW[n * SWS + h]);
#pragma unroll
                for (int t = 0; t < TG; t++)
                    acc[t][n] += x[t].x * wv.x + x[t].y * wv.y
                               + x[t].z * wv.z + x[t].w * wv.w;
            }
        }

        // --- butterfly reduce across lanes; lanes 0..6 write logits ---
#pragma unroll
        for (int t = 0; t < TG; t++) {
            float v = 0.0f;
#pragma unroll
            for (int n = 0; n < NL; n++) {
                float s = acc[t][n];
                s += __shfl_xor_sync(0xffffffffu, s, 16);
                s += __shfl_xor_sync(0xffffffffu, s, 8);
                s += __shfl_xor_sync(0xffffffffu, s, 4);
                s += __shfl_xor_sync(0xffffffffu, s, 2);
                s += __shfl_xor_sync(0xffffffffu, s, 1);
                if (lane == n) v = s;   // constant-index select, no spill
            }
            if (lane < NL)
                out[(size_t)(tok0 + t) * NL + lane] = v + bias_r;
        }
    }
}

// ---------------------------------------------------------------------------
extern "C" void kernel_launch(void* const* d_in, const int* in_sizes, int n_in,
                              void* d_out, int out_size) {
    const float* bert  = (const float*)d_in[0];
    const float* comet = (const float*)d_in[1];
    const int*   valid = (const int*)d_in[2];
    const float* w     = (const float*)d_in[3];
    const float* bias  = (const float*)d_in[4];
    float*       out   = (float*)d_out;

    build_idx_kernel<<<B, 32>>>(valid);

    const int smem = NL * SWS * (int)sizeof(float);  // 50288 B
    cudaFuncSetAttribute(tag_kernel,
                         cudaFuncAttributeMaxDynamicSharedMemorySize, smem);

    // 256 blocks * 8 warps = 2048 warps; ngroups = 4096 -> exactly 2
    // groups per warp, zero warp-level imbalance. <=2 blocks/SM, one wave.
    const int grid = 256;
    tag_kernel<<<grid, TPB, smem>>>(bert, comet, w, bias, out, grid * WPB);
}